// round 13
// baseline (speedup 1.0000x reference)
#include <cuda_runtime.h>
#include <cuda_fp16.h>
#include <cstdint>

#define BB 8
#define CC 64
#define NN 4096
#define CI 8
#define SPLITK 8

// ---------------- scratch (no allocation allowed) ----------------
__device__ __align__(16) __half g_qh[BB * NN * CI];          // [b][n][8]
__device__ __align__(16) __half g_kh[BB * NN * CI];          // [b][m][8], pre-scaled log2e/sqrt(8)
__device__ __align__(16) __half g_vt[BB * CI * NN];          // [b][i][n]  (V transposed)
__device__ __align__(16) float  g_pA[SPLITK * BB * NN * CI]; // [s][b][m][8] partial P@V
__device__ __align__(16) float  g_pD[SPLITK * BB * NN];      // [s][b][m]   partial denom
__device__ int g_cnt[BB * 32];                               // split-K counters (self-reset)

// ---------------- mma helpers (baseline sm_80+ features only) --------------
__device__ __forceinline__ void mma_s_f16(uint32_t& d0, uint32_t& d1,
                                          uint32_t a0, uint32_t a1, uint32_t b0) {
    asm("mma.sync.aligned.m16n8k8.row.col.f16.f16.f16.f16 "
        "{%0,%1}, {%2,%3}, {%4}, {%5,%6};"
        : "=r"(d0), "=r"(d1)
        : "r"(a0), "r"(a1), "r"(b0), "r"(0u), "r"(0u));
}
__device__ __forceinline__ void mma_pv_f16(uint32_t& c0, uint32_t& c1,
                                           uint32_t a0, uint32_t a1, uint32_t a2, uint32_t a3,
                                           uint32_t b0, uint32_t b1) {
    asm("mma.sync.aligned.m16n8k16.row.col.f16.f16.f16.f16 "
        "{%0,%1}, {%2,%3,%4,%5}, {%6,%7}, {%0,%1};"
        : "+r"(c0), "+r"(c1)
        : "r"(a0), "r"(a1), "r"(a2), "r"(a3), "r"(b0), "r"(b1));
}
__device__ __forceinline__ uint32_t hadd2u(uint32_t a, uint32_t b) {
    __half2 r = __hadd2(*reinterpret_cast<__half2*>(&a), *reinterpret_cast<__half2*>(&b));
    return *reinterpret_cast<uint32_t*>(&r);
}
__device__ __forceinline__ float2 h2f2(uint32_t a) {
    return __half22float2(*reinterpret_cast<__half2*>(&a));
}
// degree-3 polynomial 2^x on the fma pipe (3 HFMA2), x in ~[-1.6, 1.6]
__device__ __forceinline__ uint32_t exp2_poly3(uint32_t xu) {
    const __half2 c3 = __floats2half2_rn(0.0558f, 0.0558f);
    const __half2 c2 = __floats2half2_rn(0.2402f, 0.2402f);
    const __half2 c1 = __floats2half2_rn(0.6932f, 0.6932f);
    const __half2 c0 = __floats2half2_rn(1.0f, 1.0f);
    __half2 x = *reinterpret_cast<__half2*>(&xu);
    __half2 p = __hfma2(c3, x, c2);
    p = __hfma2(p, x, c1);
    p = __hfma2(p, x, c0);
    return *reinterpret_cast<uint32_t*>(&p);
}

// ---------------- kernel 1: q/k/v projections (4-way c-split, 128-thr) -----
__global__ void __launch_bounds__(128) proj_kernel(const float* __restrict__ x,
                                                   const float* __restrict__ Wq,
                                                   const float* __restrict__ Wk,
                                                   const float* __restrict__ Wv) {
    __shared__ float swq[CI * CC], swk[CI * CC], swv[CI * CC];
    __shared__ __half sv[CI][32];
    int tid = threadIdx.x;
    for (int i = tid; i < CI * CC; i += 128) {
        swq[i] = Wq[i]; swk[i] = Wk[i]; swv[i] = Wv[i];
    }
    __syncthreads();

    int wid = tid >> 5, lane = tid & 31;
    int quarter = lane >> 3, nl = lane & 7;
    int slot = blockIdx.x * 32 + wid * 8 + nl;     // grid 1024 -> 32768 slots
    int b = slot >> 12, n = slot & (NN - 1);
    int nloc = (wid << 3) | nl;                    // 0..31

    float q[CI], k[CI], v[CI];
#pragma unroll
    for (int i = 0; i < CI; i++) { q[i] = 0.f; k[i] = 0.f; v[i] = 0.f; }

    const float* xp = x + (size_t)b * CC * NN + n;
    int c0 = quarter * 16;
#pragma unroll
    for (int j = 0; j < 16; j++) {
        int c = c0 + j;
        float xv = xp[(size_t)c * NN];
#pragma unroll
        for (int i = 0; i < CI; i++) {
            q[i] = fmaf(swq[i * CC + c], xv, q[i]);
            k[i] = fmaf(swk[i * CC + c], xv, k[i]);
            v[i] = fmaf(swv[i * CC + c], xv, v[i]);
        }
    }
#pragma unroll
    for (int i = 0; i < CI; i++) {
        q[i] += __shfl_xor_sync(0xffffffffu, q[i], 8);
        k[i] += __shfl_xor_sync(0xffffffffu, k[i], 8);
        v[i] += __shfl_xor_sync(0xffffffffu, v[i], 8);
        q[i] += __shfl_xor_sync(0xffffffffu, q[i], 16);
        k[i] += __shfl_xor_sync(0xffffffffu, k[i], 16);
        v[i] += __shfl_xor_sync(0xffffffffu, v[i], 16);
    }
    if (quarter == 0) {
        const float KS = 0.51006971f;  // log2(e)/sqrt(8)
        size_t base = ((size_t)b * NN + n) * CI;
        __half2 qh[4], kh[4];
#pragma unroll
        for (int i = 0; i < 4; i++) {
            qh[i] = __floats2half2_rn(q[2 * i], q[2 * i + 1]);
            kh[i] = __floats2half2_rn(k[2 * i] * KS, k[2 * i + 1] * KS);
        }
        *reinterpret_cast<uint4*>(&g_qh[base]) = *reinterpret_cast<uint4*>(qh);
        *reinterpret_cast<uint4*>(&g_kh[base]) = *reinterpret_cast<uint4*>(kh);
#pragma unroll
        for (int i = 0; i < CI; i++) sv[i][nloc] = __float2half_rn(v[i]);
    }
    __syncthreads();
    if (tid < 32) {
        int row = tid >> 2, chunk = tid & 3;
        int nbase = (blockIdx.x & 127) * 32;
        int bb = blockIdx.x >> 7;
        *reinterpret_cast<uint4*>(g_vt + ((size_t)bb * CI + row) * NN + nbase + chunk * 8) =
            *reinterpret_cast<const uint4*>(&sv[row][chunk * 8]);
    }
}

// ---------------- kernel 2: resident-slice FA2, MIO-diet edition -----------
// grid 2048: b = bx>>8, mt = (bx>>3)&31 (128 m rows), s8 = bx&7 (512 n each).
// 128 threads = 4 warps; warp w owns m rows [m0+32w, +32) as two 16-row tiles.
// Q and V live in smem in a CHUNK-MAJOR PERMUTED layout: for chunk ci (16 n),
// thread slot (g, cp) finds its two fragment words contiguous at
//   perm[ (ci*8 + g)*4 + cp ]   (one uint2 = one LDS.64).
// Mainloop: per chunk = 2 LDS.64 + 4 S-MMA + 8 poly-exp + 2 PV-MMA + 8 HADD2.
// ZERO MUFU, ZERO barriers, ZERO global loads in the mainloop.
__global__ void __launch_bounds__(128, 6) attn_kernel(const float* __restrict__ x,
                                                      const float* __restrict__ Wout,
                                                      float* __restrict__ out) {
    __shared__ __align__(16) uint32_t sQp[4096];     // permuted Q slice, 8KB (u32 view)
    __shared__ __align__(16) uint32_t sVp[4096];     // permuted Vt slice, 8KB
    __shared__ float sAtt[128 * 9];
    __shared__ float sW[CC * CI];
    __shared__ int s_old;

    int tid = threadIdx.x, wid = tid >> 5, lane = tid & 31;
    int gid = lane >> 2, cp = lane & 3;
    int b = blockIdx.x >> 8, mt = (blockIdx.x >> 3) & 31, s8 = blockIdx.x & 7;
    int m0 = mt * 128;
    int nbase = s8 * 512;

    int mrowA = m0 + wid * 32 + gid;     // tile A rows: mrowA, mrowA+8
    int mrowB = mrowA + 16;              // tile B rows: mrowB, mrowB+8
    uint32_t kA0 = *reinterpret_cast<const uint32_t*>(
        &g_kh[((size_t)b * NN + mrowA) * CI + 2 * cp]);
    uint32_t kA1 = *reinterpret_cast<const uint32_t*>(
        &g_kh[((size_t)b * NN + mrowA + 8) * CI + 2 * cp]);
    uint32_t kB0 = *reinterpret_cast<const uint32_t*>(
        &g_kh[((size_t)b * NN + mrowB) * CI + 2 * cp]);
    uint32_t kB1 = *reinterpret_cast<const uint32_t*>(
        &g_kh[((size_t)b * NN + mrowB + 8) * CI + 2 * cp]);

    // ---- preload with permutation ----
    // Q: row n (0..511) has 4 u32 pairs p[j] (halves 2j, 2j+1).
    //    ci = n>>4, g = n&7, hi = (n>>3)&1 -> sQp[((ci*8+g)*4 + j)*2 + hi] = p[j]
    {
        const uint4* qg = reinterpret_cast<const uint4*>(g_qh + (size_t)b * NN * CI) + nbase;
#pragma unroll
        for (int i = 0; i < 4; i++) {
            int n = tid + i * 128;
            uint4 row = qg[n];
            int ci = n >> 4, g = n & 7, hi = (n >> 3) & 1;
            int s = ((ci * 8 + g) * 4) * 2 + hi;
            sQp[s + 0] = row.x;
            sQp[s + 2] = row.y;
            sQp[s + 4] = row.z;
            sQp[s + 6] = row.w;
        }
        // V: group idx (0..511): r = idx>>6 (channel), cgrp = idx&63 (8-col group)
        //    ci = cgrp>>1, h = cgrp&1; pair j -> sVp[((ci*8+r)*4 + j)*2 + h]
        const __half* vg = g_vt + (size_t)b * CI * NN;
#pragma unroll
        for (int i = 0; i < 4; i++) {
            int idx = tid + i * 128;
            int r = idx >> 6, cgrp = idx & 63;
            uint4 row = *reinterpret_cast<const uint4*>(vg + (size_t)r * NN + nbase + cgrp * 8);
            int ci = cgrp >> 1, h = cgrp & 1;
            int s = ((ci * 8 + r) * 4) * 2 + h;
            sVp[s + 0] = row.x;
            sVp[s + 2] = row.y;
            sVp[s + 4] = row.z;
            sVp[s + 6] = row.w;
        }
    }
    __syncthreads();   // the ONLY mainloop barrier

    // per-tile f16 PV accumulators, even/odd chunk streams
    uint32_t aAE0 = 0, aAE1 = 0, aAO0 = 0, aAO1 = 0;
    uint32_t aBE0 = 0, aBE1 = 0, aBO0 = 0, aBO1 = 0;
    uint32_t runA0 = 0, runA1 = 0, runB0 = 0, runB1 = 0;

    // per-thread fragment slot: (g*4 + cp) == lane, so uint2 index = ci*32 + lane
    const uint2* qPerm = reinterpret_cast<const uint2*>(sQp) + lane;
    const uint2* vPerm = reinterpret_cast<const uint2*>(sVp) + lane;

#pragma unroll
    for (int ci = 0; ci < 32; ci++) {
        uint2 qq = qPerm[ci * 32];     // .x = qL, .y = qH
        uint2 vv = vPerm[ci * 32];     // .x = vb0, .y = vb1

        uint32_t sA0, sA1, sA2, sA3, sB0, sB1, sB2, sB3;
        mma_s_f16(sA0, sA1, kA0, kA1, qq.x);
        mma_s_f16(sA2, sA3, kA0, kA1, qq.y);
        mma_s_f16(sB0, sB1, kB0, kB1, qq.x);
        mma_s_f16(sB2, sB3, kB0, kB1, qq.y);

        // all-poly exp2 on the fma pipe (zero MUFU in mainloop)
        uint32_t pA0 = exp2_poly3(sA0), pA1 = exp2_poly3(sA1);
        uint32_t pA2 = exp2_poly3(sA2), pA3 = exp2_poly3(sA3);
        uint32_t pB0 = exp2_poly3(sB0), pB1 = exp2_poly3(sB1);
        uint32_t pB2 = exp2_poly3(sB2), pB3 = exp2_poly3(sB3);

        if (ci & 1) {
            mma_pv_f16(aAO0, aAO1, pA0, pA1, pA2, pA3, vv.x, vv.y);
            mma_pv_f16(aBO0, aBO1, pB0, pB1, pB2, pB3, vv.x, vv.y);
        } else {
            mma_pv_f16(aAE0, aAE1, pA0, pA1, pA2, pA3, vv.x, vv.y);
            mma_pv_f16(aBE0, aBE1, pB0, pB1, pB2, pB3, vv.x, vv.y);
        }

        runA0 = hadd2u(runA0, hadd2u(pA0, pA2));
        runA1 = hadd2u(runA1, hadd2u(pA1, pA3));
        runB0 = hadd2u(runB0, hadd2u(pB0, pB2));
        runB1 = hadd2u(runB1, hadd2u(pB1, pB3));
    }

    // finalize denominators: quad-reduce (cp dimension) in f32
    float2 fA0 = h2f2(runA0), fA1 = h2f2(runA1);
    float2 fB0 = h2f2(runB0), fB1 = h2f2(runB1);
    float dA0 = fA0.x + fA0.y, dA1 = fA1.x + fA1.y;
    float dB0 = fB0.x + fB0.y, dB1 = fB1.x + fB1.y;
    dA0 += __shfl_xor_sync(0xffffffffu, dA0, 1);
    dA0 += __shfl_xor_sync(0xffffffffu, dA0, 2);
    dA1 += __shfl_xor_sync(0xffffffffu, dA1, 1);
    dA1 += __shfl_xor_sync(0xffffffffu, dA1, 2);
    dB0 += __shfl_xor_sync(0xffffffffu, dB0, 1);
    dB0 += __shfl_xor_sync(0xffffffffu, dB0, 2);
    dB1 += __shfl_xor_sync(0xffffffffu, dB1, 1);
    dB1 += __shfl_xor_sync(0xffffffffu, dB1, 2);

    // combine E/O accumulators in f32 and store partials
    {
        size_t rb = ((size_t)s8 * BB + b) * NN;
        float2 e, o;
        e = h2f2(aAE0); o = h2f2(aAO0);
        *reinterpret_cast<float2*>(&g_pA[(rb + mrowA) * CI + 2 * cp]) =
            make_float2(e.x + o.x, e.y + o.y);
        e = h2f2(aAE1); o = h2f2(aAO1);
        *reinterpret_cast<float2*>(&g_pA[(rb + mrowA + 8) * CI + 2 * cp]) =
            make_float2(e.x + o.x, e.y + o.y);
        e = h2f2(aBE0); o = h2f2(aBO0);
        *reinterpret_cast<float2*>(&g_pA[(rb + mrowB) * CI + 2 * cp]) =
            make_float2(e.x + o.x, e.y + o.y);
        e = h2f2(aBE1); o = h2f2(aBO1);
        *reinterpret_cast<float2*>(&g_pA[(rb + mrowB + 8) * CI + 2 * cp]) =
            make_float2(e.x + o.x, e.y + o.y);
        if (cp == 0) {
            g_pD[rb + mrowA] = dA0;
            g_pD[rb + mrowA + 8] = dA1;
            g_pD[rb + mrowB] = dB0;
            g_pD[rb + mrowB + 8] = dB1;
        }
    }
    __threadfence();
    __syncthreads();
    if (tid == 0) s_old = atomicAdd(&g_cnt[b * 32 + mt], 1);
    __syncthreads();
    if (s_old != SPLITK - 1) return;       // last-arriving CTA merges + epilogue
    if (tid == 0) g_cnt[b * 32 + mt] = 0;  // reset for next (graph-replayed) launch
    __threadfence();

    for (int i = tid; i < CC * CI; i += 128) sW[i] = Wout[i];
    {
        int m = m0 + tid;                  // 128 threads, 1 m-row each
        float acc[CI] = {0, 0, 0, 0, 0, 0, 0, 0};
        float den = 0.f;
#pragma unroll
        for (int qq = 0; qq < SPLITK; qq++) {
            size_t rb = ((size_t)qq * BB + b) * NN + m;
            const float4* a = reinterpret_cast<const float4*>(&g_pA[rb * CI]);
            float4 x0 = a[0], x1 = a[1];
            acc[0] += x0.x; acc[1] += x0.y; acc[2] += x0.z; acc[3] += x0.w;
            acc[4] += x1.x; acc[5] += x1.y; acc[6] += x1.z; acc[7] += x1.w;
            den += g_pD[rb];
        }
        float inv = 1.0f / den;
#pragma unroll
        for (int i = 0; i < CI; i++) sAtt[tid * 9 + i] = acc[i] * inv;
    }
    __syncthreads();

    // epilogue: out = x + 0.1 * Wout @ att  (1 m-row per thread, 64 channels)
    float att[CI];
#pragma unroll
    for (int i = 0; i < CI; i++) att[i] = sAtt[tid * 9 + i];

    int m = m0 + tid;
    const float* xp = x + (size_t)b * CC * NN + m;
    float* op = out + (size_t)b * CC * NN + m;
#pragma unroll 8
    for (int c = 0; c < CC; c++) {
        float o = 0.f;
#pragma unroll
        for (int i = 0; i < CI; i++) o = fmaf(sW[c * CI + i], att[i], o);
        op[(size_t)c * NN] = fmaf(0.1f, o, xp[(size_t)c * NN]);
    }
}

// ---------------- launch ----------------
extern "C" void kernel_launch(void* const* d_in, const int* in_sizes, int n_in,
                              void* d_out, int out_size) {
    const float* x = (const float*)d_in[0];
    const float* Wq = (const float*)d_in[1];
    const float* Wk = (const float*)d_in[2];
    const float* Wv = (const float*)d_in[3];
    const float* Wout = (const float*)d_in[4];
    float* out = (float*)d_out;

    proj_kernel<<<1024, 128>>>(x, Wq, Wk, Wv);
    attn_kernel<<<2048, 128>>>(x, Wout, out);
}

// round 14
// speedup vs baseline: 1.0007x; 1.0007x over previous
#include <cuda_runtime.h>
#include <cstdint>

#define BB 8
#define CC 64
#define NN 4096
#define CI 8
#define NF 165               // 1 + 8 + 36 + 120 features (deg <= 3)
#define NSP 64               // n-splits for moment partials
#define MPS (NF * 9)         // 1485 moments (8 v-rows + ones row)

// ---------------- scratch (no allocation allowed) ----------------
__device__ __align__(16) float g_qf[BB * NN * 8];        // q  [b][n][8]
__device__ __align__(16) float g_kf[BB * NN * 8];        // k/sqrt(8) [b][m][8]
__device__ __align__(16) float g_vf[BB * NN * 8];        // v  [b][n][8]
__device__ __align__(16) float g_Mp[BB * NSP * MPS];     // moment partials
__device__ __align__(16) float g_Mf[BB * MPS];           // final moments

// ---------------- f32x2 helpers ----------------
__device__ __forceinline__ unsigned long long pk2(float lo, float hi) {
    unsigned long long r;
    asm("mov.b64 %0, {%1,%2};" : "=l"(r) : "f"(lo), "f"(hi));
    return r;
}
__device__ __forceinline__ unsigned long long ffma2(unsigned long long a, unsigned long long b,
                                                    unsigned long long c) {
    unsigned long long d;
    asm("fma.rn.f32x2 %0, %1, %2, %3;" : "=l"(d) : "l"(a), "l"(b), "l"(c));
    return d;
}
__device__ __forceinline__ void up2(unsigned long long p, float& lo, float& hi) {
    asm("mov.b64 {%0,%1}, %2;" : "=f"(lo), "=f"(hi) : "l"(p));
}

// ---------------- kernel 1: q/k/v projections (f32 out) --------------------
__global__ void __launch_bounds__(128) proj_kernel(const float* __restrict__ x,
                                                   const float* __restrict__ Wq,
                                                   const float* __restrict__ Wk,
                                                   const float* __restrict__ Wv) {
    __shared__ float swq[CI * CC], swk[CI * CC], swv[CI * CC];
    int tid = threadIdx.x;
    for (int i = tid; i < CI * CC; i += 128) {
        swq[i] = Wq[i]; swk[i] = Wk[i]; swv[i] = Wv[i];
    }
    __syncthreads();

    int wid = tid >> 5, lane = tid & 31;
    int quarter = lane >> 3, nl = lane & 7;
    int slot = blockIdx.x * 32 + wid * 8 + nl;     // grid 1024 -> 32768 slots
    int b = slot >> 12, n = slot & (NN - 1);

    float q[CI], k[CI], v[CI];
#pragma unroll
    for (int i = 0; i < CI; i++) { q[i] = 0.f; k[i] = 0.f; v[i] = 0.f; }

    const float* xp = x + (size_t)b * CC * NN + n;
    int c0 = quarter * 16;
#pragma unroll
    for (int j = 0; j < 16; j++) {
        int c = c0 + j;
        float xv = xp[(size_t)c * NN];
#pragma unroll
        for (int i = 0; i < CI; i++) {
            q[i] = fmaf(swq[i * CC + c], xv, q[i]);
            k[i] = fmaf(swk[i * CC + c], xv, k[i]);
            v[i] = fmaf(swv[i * CC + c], xv, v[i]);
        }
    }
#pragma unroll
    for (int i = 0; i < CI; i++) {
        q[i] += __shfl_xor_sync(0xffffffffu, q[i], 8);
        k[i] += __shfl_xor_sync(0xffffffffu, k[i], 8);
        v[i] += __shfl_xor_sync(0xffffffffu, v[i], 8);
        q[i] += __shfl_xor_sync(0xffffffffu, q[i], 16);
        k[i] += __shfl_xor_sync(0xffffffffu, k[i], 16);
        v[i] += __shfl_xor_sync(0xffffffffu, v[i], 16);
    }
    if (quarter == 0) {
        const float KS = 0.35355339f;   // 1/sqrt(8) folded into k
        size_t base = ((size_t)b * NN + n) * 8;
        *reinterpret_cast<float4*>(&g_qf[base]) = make_float4(q[0], q[1], q[2], q[3]);
        *reinterpret_cast<float4*>(&g_qf[base + 4]) = make_float4(q[4], q[5], q[6], q[7]);
        *reinterpret_cast<float4*>(&g_kf[base]) =
            make_float4(k[0] * KS, k[1] * KS, k[2] * KS, k[3] * KS);
        *reinterpret_cast<float4*>(&g_kf[base + 4]) =
            make_float4(k[4] * KS, k[5] * KS, k[6] * KS, k[7] * KS);
        *reinterpret_cast<float4*>(&g_vf[base]) = make_float4(v[0], v[1], v[2], v[3]);
        *reinterpret_cast<float4*>(&g_vf[base + 4]) = make_float4(v[4], v[5], v[6], v[7]);
    }
}

// ---------------- kernel 2: moments M[i,f] = sum_n v_i(n) w_f psi_f(q_n) ---
// grid 512 (b = bx>>6, sp = bx&63; 64 n each), 192 threads.
// Gen phase: 3 parts x 64 n write weighted q-features into smem.
// Accum phase: 165 f-threads accumulate over 64 n via f32x2 (n-pairs).
__global__ void __launch_bounds__(192) moments_kernel() {
    __shared__ float sPsi[64][169];     // [n][feature], padded stride
    __shared__ float2 sv2[32][9];       // [n-pair][i]: (v[2np][i], v[2np+1][i]); i=8 -> ones

    int tid = threadIdx.x;
    int b = blockIdx.x >> 6, sp = blockIdx.x & 63;
    int nbase = sp * 64;
    int part = tid >> 6, nn = tid & 63;
    int n = nbase + nn;

    // load q for this n
    float u[8];
    {
        size_t base = ((size_t)b * NN + n) * 8;
        float4 a = *reinterpret_cast<const float4*>(&g_qf[base]);
        float4 c = *reinterpret_cast<const float4*>(&g_qf[base + 4]);
        u[0] = a.x; u[1] = a.y; u[2] = a.z; u[3] = a.w;
        u[4] = c.x; u[5] = c.y; u[6] = c.z; u[7] = c.w;
    }

    if (part == 0) {
        // f = 0: constant; f = 1..8: linear; f = 9..44: deg-2 (weighted)
        sPsi[nn][0] = 1.0f;
#pragma unroll
        for (int i = 0; i < 8; i++) sPsi[nn][1 + i] = u[i];
        int f = 9;
#pragma unroll
        for (int i = 0; i < 8; i++)
#pragma unroll
            for (int j = i; j < 8; j++) {
                float w = (i == j) ? 0.5f : 1.0f;
                sPsi[nn][f] = w * u[i] * u[j];
                f++;
            }
        // v (+ ones) into n-pair layout
        size_t vb = ((size_t)b * NN + n) * 8;
        float4 a = *reinterpret_cast<const float4*>(&g_vf[vb]);
        float4 c = *reinterpret_cast<const float4*>(&g_vf[vb + 4]);
        float vv[9] = {a.x, a.y, a.z, a.w, c.x, c.y, c.z, c.w, 1.0f};
#pragma unroll
        for (int i = 0; i < 9; i++)
            reinterpret_cast<float*>(&sv2[nn >> 1][i])[nn & 1] = vv[i];
    } else if (part == 1) {
        // deg-3, i = 0..1 (64 features), f starts at 45
        int f = 45;
#pragma unroll
        for (int i = 0; i < 2; i++)
#pragma unroll
            for (int j = i; j < 8; j++) {
                float dij = u[i] * u[j];
#pragma unroll
                for (int l = j; l < 8; l++) {
                    float w = (i == j && j == l) ? 0.16666667f
                              : ((i == j || j == l) ? 0.5f : 1.0f);
                    sPsi[nn][f] = w * dij * u[l];
                    f++;
                }
            }
    } else {
        // deg-3, i = 2..7 (56 features), f starts at 109
        int f = 109;
#pragma unroll
        for (int i = 2; i < 8; i++)
#pragma unroll
            for (int j = i; j < 8; j++) {
                float dij = u[i] * u[j];
#pragma unroll
                for (int l = j; l < 8; l++) {
                    float w = (i == j && j == l) ? 0.16666667f
                              : ((i == j || j == l) ? 0.5f : 1.0f);
                    sPsi[nn][f] = w * dij * u[l];
                    f++;
                }
            }
    }
    __syncthreads();

    if (tid < NF) {
        int f = tid;
        unsigned long long acc[9];
#pragma unroll
        for (int i = 0; i < 9; i++) acc[i] = 0ull;
#pragma unroll 4
        for (int np = 0; np < 32; np++) {
            float p0 = sPsi[2 * np][f];
            float p1 = sPsi[2 * np + 1][f];
            unsigned long long pp = pk2(p0, p1);
            const unsigned long long* vp =
                reinterpret_cast<const unsigned long long*>(&sv2[np][0]);
#pragma unroll
            for (int i = 0; i < 9; i++) acc[i] = ffma2(pp, vp[i], acc[i]);
        }
        size_t ob = ((size_t)b * NSP + sp) * MPS + (size_t)f * 9;
#pragma unroll
        for (int i = 0; i < 9; i++) {
            float lo, hi;
            up2(acc[i], lo, hi);
            g_Mp[ob + i] = lo + hi;
        }
    }
}

// ---------------- kernel 2b: reduce partials -------------------------------
__global__ void __launch_bounds__(256) reduce_kernel() {
    int b = blockIdx.x, tid = threadIdx.x;
    for (int out = tid; out < MPS; out += 256) {
        float s = 0.f;
#pragma unroll 8
        for (int sp = 0; sp < NSP; sp++)
            s += g_Mp[((size_t)b * NSP + sp) * MPS + out];
        g_Mf[(size_t)b * MPS + out] = s;
    }
}

// ---------------- kernel 3: eval + normalize + Wout epilogue ---------------
// grid 128 (b = bx>>4, mt = bx&15; 256 m each), 256 threads.
// thread (mm = tid&127, fh = tid>>7): two m's (m0+mm, m0+mm+128), half features.
// fh0: f 0..80 (const+lin+deg2 + deg3 i=0); fh1: f 81..164 (deg3 i=1..7).
#define ACC9(MON, FI)                                            \
    do {                                                         \
        const float* Mf_ = sM + (FI) * 9;                        \
        float mA_ = (MON##A), mB_ = (MON##B);                    \
        _Pragma("unroll")                                        \
        for (int t_ = 0; t_ < 9; t_++) {                         \
            float mv_ = Mf_[t_];                                 \
            accA[t_] = fmaf(mA_, mv_, accA[t_]);                 \
            accB[t_] = fmaf(mB_, mv_, accB[t_]);                 \
        }                                                        \
    } while (0)

__global__ void __launch_bounds__(256) eval_kernel(const float* __restrict__ x,
                                                   const float* __restrict__ Wout,
                                                   float* __restrict__ out) {
    __shared__ float sM[MPS];
    __shared__ float sW[CC * CI];
    __shared__ float sAtt[256][9];

    int tid = threadIdx.x;
    int b = blockIdx.x >> 4, mt = blockIdx.x & 15;
    int m0 = mt * 256;

    for (int i = tid; i < MPS; i += 256) sM[i] = g_Mf[(size_t)b * MPS + i];
    for (int i = tid; i < CC * CI; i += 256) sW[i] = Wout[i];
    __syncthreads();

    int mm = tid & 127, fh = tid >> 7;
    int mA = m0 + mm, mB = m0 + mm + 128;

    float uA[8], uB[8];
    {
        size_t ba = ((size_t)b * NN + mA) * 8;
        size_t bb2 = ((size_t)b * NN + mB) * 8;
        float4 a0 = *reinterpret_cast<const float4*>(&g_kf[ba]);
        float4 a1 = *reinterpret_cast<const float4*>(&g_kf[ba + 4]);
        float4 b0 = *reinterpret_cast<const float4*>(&g_kf[bb2]);
        float4 b1 = *reinterpret_cast<const float4*>(&g_kf[bb2 + 4]);
        uA[0] = a0.x; uA[1] = a0.y; uA[2] = a0.z; uA[3] = a0.w;
        uA[4] = a1.x; uA[5] = a1.y; uA[6] = a1.z; uA[7] = a1.w;
        uB[0] = b0.x; uB[1] = b0.y; uB[2] = b0.z; uB[3] = b0.w;
        uB[4] = b1.x; uB[5] = b1.y; uB[6] = b1.z; uB[7] = b1.w;
    }

    float accA[9], accB[9];
#pragma unroll
    for (int i = 0; i < 9; i++) { accA[i] = 0.f; accB[i] = 0.f; }

    if (fh == 0) {
        // f = 0
        float oneA = 1.0f, oneB = 1.0f;
        ACC9(one, 0);
        // f = 1..8
#pragma unroll
        for (int i = 0; i < 8; i++) {
            float lA = uA[i], lB = uB[i];
            ACC9(l, 1 + i);
        }
        // deg-2: f = 9..44 (plain monomials, no weights on k-side)
        int f = 9;
#pragma unroll
        for (int i = 0; i < 8; i++)
#pragma unroll
            for (int j = i; j < 8; j++) {
                float dA = uA[i] * uA[j], dB = uB[i] * uB[j];
                ACC9(d, f);
                f++;
            }
        // deg-3, i = 0: f = 45..80
        f = 45;
        {
            const int i = 0;
#pragma unroll
            for (int j = i; j < 8; j++) {
                float pA = uA[i] * uA[j], pB = uB[i] * uB[j];
#pragma unroll
                for (int l = j; l < 8; l++) {
                    float tA = pA * uA[l], tB = pB * uB[l];
                    ACC9(t, f);
                    f++;
                }
            }
        }
    } else {
        // deg-3, i = 1..7: f = 81..164
        int f = 81;
#pragma unroll
        for (int i = 1; i < 8; i++)
#pragma unroll
            for (int j = i; j < 8; j++) {
                float pA = uA[i] * uA[j], pB = uB[i] * uB[j];
#pragma unroll
                for (int l = j; l < 8; l++) {
                    float tA = pA * uA[l], tB = pB * uB[l];
                    ACC9(t, f);
                    f++;
                }
            }
        // publish fh1 partials
#pragma unroll
        for (int i = 0; i < 9; i++) {
            sAtt[mm][i] = accA[i];
            sAtt[mm + 128][i] = accB[i];
        }
    }
    __syncthreads();

    if (fh == 0) {
        // combine halves, normalize, write att
        float dA = accA[8] + sAtt[mm][8];
        float dB = accB[8] + sAtt[mm + 128][8];
        float invA = 1.0f / dA, invB = 1.0f / dB;
        float aA[8], aB[8];
#pragma unroll
        for (int i = 0; i < 8; i++) {
            aA[i] = (accA[i] + sAtt[mm][i]) * invA;
            aB[i] = (accB[i] + sAtt[mm + 128][i]) * invB;
        }
        __syncthreads();   // fh1 done reading nothing; safe to overwrite
#pragma unroll
        for (int i = 0; i < 8; i++) {
            sAtt[mm][i] = aA[i];
            sAtt[mm + 128][i] = aB[i];
        }
    } else {
        __syncthreads();
    }
    __syncthreads();

    // epilogue: out = x + 0.1 * Wout @ att ; thread tid -> m = m0 + tid
    float att[CI];
#pragma unroll
    for (int i = 0; i < CI; i++) att[i] = sAtt[tid][i];

    int m = m0 + tid;
    const float* xp = x + (size_t)b * CC * NN + m;
    float* op = out + (size_t)b * CC * NN + m;
#pragma unroll 8
    for (int c = 0; c < CC; c++) {
        float o = 0.f;
#pragma unroll
        for (int i = 0; i < CI; i++) o = fmaf(sW[c * CI + i], att[i], o);
        op[(size_t)c * NN] = fmaf(0.1f, o, xp[(size_t)c * NN]);
    }
}

// ---------------- launch ----------------
extern "C" void kernel_launch(void* const* d_in, const int* in_sizes, int n_in,
                              void* d_out, int out_size) {
    const float* x = (const float*)d_in[0];
    const float* Wq = (const float*)d_in[1];
    const float* Wk = (const float*)d_in[2];
    const float* Wv = (const float*)d_in[3];
    const float* Wout = (const float*)d_in[4];
    float* out = (float*)d_out;

    proj_kernel<<<1024, 128>>>(x, Wq, Wk, Wv);
    moments_kernel<<<512, 192>>>();
    reduce_kernel<<<8, 256>>>();
    eval_kernel<<<128, 256>>>(x, Wout, out);
}

// round 15
// speedup vs baseline: 1.5246x; 1.5236x over previous
#include <cuda_runtime.h>
#include <cstdint>

#define BB 8
#define CC 64
#define NN 4096
#define CI 8
#define NF 165               // 1 + 8 + 36 + 120 features (deg <= 3)
#define NSP 128              // n-splits for moment partials (32 n each)
#define MPS (NF * 9)         // 1485 moments, layout [i][f] (i-major planes)

// ---------------- scratch (no allocation allowed) ----------------
__device__ __align__(16) float g_qf[BB * NN * 8];        // q  [b][n][8]
__device__ __align__(16) float g_kf[BB * NN * 8];        // k/sqrt(8) [b][m][8]
__device__ __align__(16) float g_vf[BB * NN * 8];        // v  [b][n][8]
__device__ __align__(16) float g_Mp[BB * NSP * MPS];     // moment partials
__device__ __align__(16) float g_Mf[BB * MPS];           // final moments

// ---------------- f32x2 helpers ----------------
__device__ __forceinline__ unsigned long long ffma2(unsigned long long a, unsigned long long b,
                                                    unsigned long long c) {
    unsigned long long d;
    asm("fma.rn.f32x2 %0, %1, %2, %3;" : "=l"(d) : "l"(a), "l"(b), "l"(c));
    return d;
}
__device__ __forceinline__ void up2(unsigned long long p, float& lo, float& hi) {
    asm("mov.b64 {%0,%1}, %2;" : "=f"(lo), "=f"(hi) : "l"(p));
}

// weighted deg-3 feature generation (q side), compile-time range -> unrolled
template <int I0, int I1, int F0>
__device__ __forceinline__ void gen3(float* sPsiT, int nn, const float (&u)[8]) {
    int f = F0;
#pragma unroll
    for (int i = I0; i < I1; i++)
#pragma unroll
        for (int j = i; j < 8; j++) {
            float dij = u[i] * u[j];
#pragma unroll
            for (int l = j; l < 8; l++) {
                float w = (i == j && j == l) ? 0.16666667f
                          : ((i == j || j == l) ? 0.5f : 1.0f);
                sPsiT[f * 34 + nn] = w * dij * u[l];
                f++;
            }
        }
}

// accumulate one feature's 9 moments (k side): 3 LDS from f-major sM2[f][12]
__device__ __forceinline__ void acc1(float* acc, const float* sM2, int f, float mon) {
    const float4* Mp = reinterpret_cast<const float4*>(&sM2[f * 12]);
    float4 a = Mp[0], b = Mp[1];
    float m8 = sM2[f * 12 + 8];
    acc[0] = fmaf(mon, a.x, acc[0]);
    acc[1] = fmaf(mon, a.y, acc[1]);
    acc[2] = fmaf(mon, a.z, acc[2]);
    acc[3] = fmaf(mon, a.w, acc[3]);
    acc[4] = fmaf(mon, b.x, acc[4]);
    acc[5] = fmaf(mon, b.y, acc[5]);
    acc[6] = fmaf(mon, b.z, acc[6]);
    acc[7] = fmaf(mon, b.w, acc[7]);
    acc[8] = fmaf(mon, m8, acc[8]);
}
template <int I0, int I1, int F0>
__device__ __forceinline__ void acc3(float* acc, const float* sM2, const float (&u)[8]) {
    int f = F0;
#pragma unroll
    for (int i = I0; i < I1; i++)
#pragma unroll
        for (int j = i; j < 8; j++) {
            float dij = u[i] * u[j];
#pragma unroll
            for (int l = j; l < 8; l++) {
                acc1(acc, sM2, f, dij * u[l]);
                f++;
            }
        }
}

// ---------------- kernel 1: q/k/v projections (f32 out) --------------------
__global__ void __launch_bounds__(128) proj_kernel(const float* __restrict__ x,
                                                   const float* __restrict__ Wq,
                                                   const float* __restrict__ Wk,
                                                   const float* __restrict__ Wv) {
    __shared__ float swq[CI * CC], swk[CI * CC], swv[CI * CC];
    int tid = threadIdx.x;
    for (int i = tid; i < CI * CC; i += 128) {
        swq[i] = Wq[i]; swk[i] = Wk[i]; swv[i] = Wv[i];
    }
    __syncthreads();

    int wid = tid >> 5, lane = tid & 31;
    int quarter = lane >> 3, nl = lane & 7;
    int slot = blockIdx.x * 32 + wid * 8 + nl;     // grid 1024 -> 32768 slots
    int b = slot >> 12, n = slot & (NN - 1);

    float q[CI], k[CI], v[CI];
#pragma unroll
    for (int i = 0; i < CI; i++) { q[i] = 0.f; k[i] = 0.f; v[i] = 0.f; }

    const float* xp = x + (size_t)b * CC * NN + n;
    int c0 = quarter * 16;
#pragma unroll
    for (int j = 0; j < 16; j++) {
        int c = c0 + j;
        float xv = xp[(size_t)c * NN];
#pragma unroll
        for (int i = 0; i < CI; i++) {
            q[i] = fmaf(swq[i * CC + c], xv, q[i]);
            k[i] = fmaf(swk[i * CC + c], xv, k[i]);
            v[i] = fmaf(swv[i * CC + c], xv, v[i]);
        }
    }
#pragma unroll
    for (int i = 0; i < CI; i++) {
        q[i] += __shfl_xor_sync(0xffffffffu, q[i], 8);
        k[i] += __shfl_xor_sync(0xffffffffu, k[i], 8);
        v[i] += __shfl_xor_sync(0xffffffffu, v[i], 8);
        q[i] += __shfl_xor_sync(0xffffffffu, q[i], 16);
        k[i] += __shfl_xor_sync(0xffffffffu, k[i], 16);
        v[i] += __shfl_xor_sync(0xffffffffu, v[i], 16);
    }
    if (quarter == 0) {
        const float KS = 0.35355339f;   // 1/sqrt(8) folded into k
        size_t base = ((size_t)b * NN + n) * 8;
        *reinterpret_cast<float4*>(&g_qf[base]) = make_float4(q[0], q[1], q[2], q[3]);
        *reinterpret_cast<float4*>(&g_qf[base + 4]) = make_float4(q[4], q[5], q[6], q[7]);
        *reinterpret_cast<float4*>(&g_kf[base]) =
            make_float4(k[0] * KS, k[1] * KS, k[2] * KS, k[3] * KS);
        *reinterpret_cast<float4*>(&g_kf[base + 4]) =
            make_float4(k[4] * KS, k[5] * KS, k[6] * KS, k[7] * KS);
        *reinterpret_cast<float4*>(&g_vf[base]) = make_float4(v[0], v[1], v[2], v[3]);
        *reinterpret_cast<float4*>(&g_vf[base + 4]) = make_float4(v[4], v[5], v[6], v[7]);
    }
}

// ---------------- kernel 2: moments M[i,f] = sum_n v_i(n) w_f psi_f(q_n) ---
// grid 1024 (b = bx>>7, sp = bx&127; 32 n each), 192 threads = 6 gen warps.
// psi stored TRANSPOSED [f][34] so the accum n-pair read is ONE aligned,
// conflict-free LDS.64 that is directly the packed f32x2 operand.
__global__ void __launch_bounds__(192) moments_kernel() {
    __shared__ __align__(16) float sPsiT[NF * 34];   // 22.4 KB
    __shared__ __align__(16) float sv[16 * 20];      // v pairs, flat, padded

    int tid = threadIdx.x;
    int b = blockIdx.x >> 7, sp = blockIdx.x & 127;
    int nbase = sp * 32;
    int part = tid >> 5, nn = tid & 31;
    int n = nbase + nn;

    float u[8];
    {
        size_t base = ((size_t)b * NN + n) * 8;
        float4 a = *reinterpret_cast<const float4*>(&g_qf[base]);
        float4 c = *reinterpret_cast<const float4*>(&g_qf[base + 4]);
        u[0] = a.x; u[1] = a.y; u[2] = a.z; u[3] = a.w;
        u[4] = c.x; u[5] = c.y; u[6] = c.z; u[7] = c.w;
    }

    if (part == 0) {
        sPsiT[0 * 34 + nn] = 1.0f;
#pragma unroll
        for (int i = 0; i < 8; i++) sPsiT[(1 + i) * 34 + nn] = u[i];
        size_t vb = ((size_t)b * NN + n) * 8;
        float4 a = *reinterpret_cast<const float4*>(&g_vf[vb]);
        float4 c = *reinterpret_cast<const float4*>(&g_vf[vb + 4]);
        float vv[9] = {a.x, a.y, a.z, a.w, c.x, c.y, c.z, c.w, 1.0f};
        int np = nn >> 1, h = nn & 1;
#pragma unroll
        for (int i = 0; i < 9; i++) sv[np * 20 + i * 2 + h] = vv[i];
    } else if (part == 1) {
        int f = 9;
#pragma unroll
        for (int i = 0; i < 8; i++)
#pragma unroll
            for (int j = i; j < 8; j++) {
                float w = (i == j) ? 0.5f : 1.0f;
                sPsiT[f * 34 + nn] = w * u[i] * u[j];
                f++;
            }
    } else if (part == 2) {
        gen3<0, 1, 45>(sPsiT, nn, u);
    } else if (part == 3) {
        gen3<1, 2, 81>(sPsiT, nn, u);
    } else if (part == 4) {
        gen3<2, 4, 109>(sPsiT, nn, u);
    } else {
        gen3<4, 8, 145>(sPsiT, nn, u);
    }
    __syncthreads();

    if (tid < NF) {
        int f = tid;
        unsigned long long acc[9];
#pragma unroll
        for (int i = 0; i < 9; i++) acc[i] = 0ull;
#pragma unroll
        for (int np = 0; np < 16; np++) {
            unsigned long long pp =
                *reinterpret_cast<const unsigned long long*>(&sPsiT[f * 34 + 2 * np]);
            const float* vv = &sv[np * 20];
            ulonglong2 v01 = *reinterpret_cast<const ulonglong2*>(vv);
            ulonglong2 v23 = *reinterpret_cast<const ulonglong2*>(vv + 4);
            ulonglong2 v45 = *reinterpret_cast<const ulonglong2*>(vv + 8);
            ulonglong2 v67 = *reinterpret_cast<const ulonglong2*>(vv + 12);
            unsigned long long v8 = *reinterpret_cast<const unsigned long long*>(vv + 16);
            acc[0] = ffma2(pp, v01.x, acc[0]);
            acc[1] = ffma2(pp, v01.y, acc[1]);
            acc[2] = ffma2(pp, v23.x, acc[2]);
            acc[3] = ffma2(pp, v23.y, acc[3]);
            acc[4] = ffma2(pp, v45.x, acc[4]);
            acc[5] = ffma2(pp, v45.y, acc[5]);
            acc[6] = ffma2(pp, v67.x, acc[6]);
            acc[7] = ffma2(pp, v67.y, acc[7]);
            acc[8] = ffma2(pp, v8, acc[8]);
        }
        size_t ob = ((size_t)b * NSP + sp) * MPS;
#pragma unroll
        for (int i = 0; i < 9; i++) {
            float lo, hi;
            up2(acc[i], lo, hi);
            g_Mp[ob + (size_t)i * NF + f] = lo + hi;   // [i][f]: coalesced across f
        }
    }
}

// ---------------- kernel 2b: reduce partials (48 CTAs, MLP-deep) -----------
__global__ void __launch_bounds__(256) reduce_kernel() {
    int b = blockIdx.x / 6, chunk = blockIdx.x % 6;
    if (threadIdx.x >= 248) return;
    int out = chunk * 248 + threadIdx.x;
    if (out >= MPS) return;
    float s = 0.f;
#pragma unroll 32
    for (int sp = 0; sp < NSP; sp++)
        s += g_Mp[((size_t)b * NSP + sp) * MPS + out];
    g_Mf[(size_t)b * MPS + out] = s;
}

// ---------------- kernel 3: eval + normalize + Wout epilogue ---------------
// grid 512 (b = bx>>6, mt = bx&63; 64 m each), 256 threads:
// mm = tid&63 (one m per thread), fq = tid>>6 (4-way feature split:
// fq0 f0..44 const+lin+deg2; fq1 deg3 i=0; fq2 i=1..2; fq3 i=3..7).
__global__ void __launch_bounds__(256) eval_kernel(const float* __restrict__ x,
                                                   const float* __restrict__ Wout,
                                                   float* __restrict__ out) {
    __shared__ __align__(16) float sM2[NF * 12];   // f-major [f][12] (9 used)
    __shared__ float sW[CC * CI];
    __shared__ float sPart[3 * 64 * 9];
    __shared__ float sAtt[64 * 9];

    int tid = threadIdx.x;
    int b = blockIdx.x >> 6, mt = blockIdx.x & 63;
    int m0 = mt * 64;

    for (int idx = tid; idx < MPS; idx += 256) {
        int i = idx / NF, f = idx - i * NF;        // source layout [i][f]
        sM2[f * 12 + i] = g_Mf[(size_t)b * MPS + idx];
    }
    for (int i = tid; i < CC * CI; i += 256) sW[i] = Wout[i];
    __syncthreads();

    int mm = tid & 63, fq = tid >> 6;
    int m = m0 + mm;

    float u[8];
    {
        size_t base = ((size_t)b * NN + m) * 8;
        float4 a = *reinterpret_cast<const float4*>(&g_kf[base]);
        float4 c = *reinterpret_cast<const float4*>(&g_kf[base + 4]);
        u[0] = a.x; u[1] = a.y; u[2] = a.z; u[3] = a.w;
        u[4] = c.x; u[5] = c.y; u[6] = c.z; u[7] = c.w;
    }

    float acc[9];
#pragma unroll
    for (int i = 0; i < 9; i++) acc[i] = 0.f;

    if (fq == 0) {
        acc1(acc, sM2, 0, 1.0f);                   // const
#pragma unroll
        for (int i = 0; i < 8; i++) acc1(acc, sM2, 1 + i, u[i]);   // linear
        int f = 9;                                 // deg-2
#pragma unroll
        for (int i = 0; i < 8; i++)
#pragma unroll
            for (int j = i; j < 8; j++) {
                acc1(acc, sM2, f, u[i] * u[j]);
                f++;
            }
    } else if (fq == 1) {
        acc3<0, 1, 45>(acc, sM2, u);
    } else if (fq == 2) {
        acc3<1, 3, 81>(acc, sM2, u);
    } else {
        acc3<3, 8, 130>(acc, sM2, u);
    }

    if (fq > 0) {
#pragma unroll
        for (int t = 0; t < 9; t++) sPart[((fq - 1) * 64 + mm) * 9 + t] = acc[t];
    }
    __syncthreads();
    if (fq == 0) {
#pragma unroll
        for (int p = 0; p < 3; p++)
#pragma unroll
            for (int t = 0; t < 9; t++) acc[t] += sPart[(p * 64 + mm) * 9 + t];
        float inv = 1.0f / acc[8];
#pragma unroll
        for (int i = 0; i < 8; i++) sAtt[mm * 9 + i] = acc[i] * inv;
    }
    __syncthreads();

    // epilogue: out = x + 0.1 * Wout @ att ; thread (ml, cq): 16 channels
    int ml = tid & 63, cq = tid >> 6;
    float att[8];
#pragma unroll
    for (int i = 0; i < 8; i++) att[i] = sAtt[ml * 9 + i];

    int mg = m0 + ml;
    const float* xp = x + (size_t)b * CC * NN + mg;
    float* op = out + (size_t)b * CC * NN + mg;
#pragma unroll
    for (int j = 0; j < 16; j++) {
        int c = cq * 16 + j;
        float o = 0.f;
#pragma unroll
        for (int i = 0; i < 8; i++) o = fmaf(sW[c * CI + i], att[i], o);
        op[(size_t)c * NN] = fmaf(0.1f, o, xp[(size_t)c * NN]);
    }
}

// ---------------- launch ----------------
extern "C" void kernel_launch(void* const* d_in, const int* in_sizes, int n_in,
                              void* d_out, int out_size) {
    const float* x = (const float*)d_in[0];
    const float* Wq = (const float*)d_in[1];
    const float* Wk = (const float*)d_in[2];
    const float* Wv = (const float*)d_in[3];
    const float* Wout = (const float*)d_in[4];
    float* out = (float*)d_out;

    proj_kernel<<<1024, 128>>>(x, Wq, Wk, Wv);
    moments_kernel<<<1024, 192>>>();
    reduce_kernel<<<48, 256>>>();
    eval_kernel<<<512, 256>>>(x, Wout, out);
}